// round 8
// baseline (speedup 1.0000x reference)
#include <cuda_runtime.h>
#include <cuda_bf16.h>

// Fixed shapes from setup_inputs
#define BB 8
#define KK 8
#define HH 1024
#define WW 1024
#define CH 8                  // rows computed per block
#define NBY (HH / CH)         // 128 blocks along H
#define NBLOCKS (NBY * BB)    // 1024 total
#define GAMMA_C 10.0f
#define EPS_SQRT_C 1e-24f

#define NSTG 3
#define SETF (9 * WW)         // floats per row-set: I row + 8 p rows
#define DYN_SMEM (NSTG * SETF * sizeof(float))   // 108 KB

// Per-block partials: [y][b*16 + q]; q<8: nom[k], q>=8: den[k]
__device__ float g_part[NBY * BB * 16];
__device__ unsigned int g_count = 0;   // zero-init; last block resets it

__device__ __forceinline__ void cp16(float* dst, const float* src) {
    unsigned s = (unsigned)__cvta_generic_to_shared(dst);
    asm volatile("cp.async.cg.shared.global [%0], [%1], 16;" :: "r"(s), "l"(src));
}
#define CP_COMMIT() asm volatile("cp.async.commit_group;" ::: "memory")
#define CP_WAIT1()  asm volatile("cp.async.wait_group 1;" ::: "memory")

__global__ __launch_bounds__(256, 2) void clustering_fused_kernel(
    const float* __restrict__ img,      // (B,1,H,W)
    const float* __restrict__ spacing,  // (2,)
    const float* __restrict__ p,        // (B,K,H,W)
    float* __restrict__ out)
{
    extern __shared__ float sm[];       // [NSTG][9][WW]

    const int b    = blockIdx.z;
    const int h0   = blockIdx.y * CH;
    const int w0   = 4 * threadIdx.x;   // 256 threads cover W=1024 via float4
    const int idxR = (w0 + 4 < WW) ? (w0 + 4) : (WW - 1);  // right-neighbor clamp

    const float sx = spacing[0];
    const float sy = spacing[1];
    const float smin   = fminf(sx, sy);
    const float inv_sx = 1.0f / sx;
    const float inv_sy = 1.0f / sy;

    const float* __restrict__ Ib = img + (size_t)b * HH * WW;
    const float* __restrict__ pb = p   + (size_t)b * KK * HH * WW;

    // ---- row-set loader: I row + 8 p rows into stage ----
    auto load_row = [&](int stage, int h) {
        float* base = sm + stage * SETF;
        const size_t go = (size_t)h * WW + w0;
        cp16(base + w0, Ib + go);
#pragma unroll
        for (int k = 0; k < KK; k++)
            cp16(base + (k + 1) * WW + w0, pb + (size_t)k * HH * WW + go);
    };

    float nom[KK], den[KK];
#pragma unroll
    for (int k = 0; k < KK; k++) { nom[k] = 0.0f; den[k] = 0.0f; }

    // ---- prime pipeline: rows h0, h0+1 ----
    load_row(0, h0);               CP_COMMIT();
    load_row(1, h0 + 1);           CP_COMMIT();   // h0+1 <= 1017, no clamp needed

    for (int r = 0; r < CH; r++) {
        // prefetch row h0+r+2 (only rows h0..h0+CH are needed)
        if (r + 2 <= CH) {
            int hf = h0 + r + 2;
            if (hf > HH - 1) hf = HH - 1;
            load_row((r + 2) % NSTG, hf);
        }
        CP_COMMIT();               // (possibly empty) group keeps counts uniform
        CP_WAIT1();                // rows r, r+1 landed
        __syncthreads();           // visible to all threads

        const float* cur = sm + (r % NSTG) * SETF;
        const float* nxt = sm + ((r + 1) % NSTG) * SETF;

        // ---- edge weights + (1+2w), shared across all K channels ----
        const float4 iC = *(const float4*)(cur + w0);
        const float4 iN = *(const float4*)(nxt + w0);
        const float  iR = cur[idxR];

        float wE[4], tE[4];
        {
            const float ix[4] = { iN.x - iC.x, iN.y - iC.y, iN.z - iC.z, iN.w - iC.w };
            const float iy[4] = { iC.y - iC.x, iC.z - iC.y, iC.w - iC.z, iR   - iC.w };
#pragma unroll
            for (int j = 0; j < 4; j++) {
                const float gx  = ix[j] * inv_sx;
                const float gy  = iy[j] * inv_sy;
                const float gn2 = gx * gx + gy * gy;
                const float gnI = sqrtf(fmaxf(gn2, EPS_SQRT_C));
                wE[j] = 1.0f / (1.0f + GAMMA_C * gnI * smin);
                tE[j] = 1.0f + 2.0f * wE[j];
            }
        }

#pragma unroll
        for (int k = 0; k < KK; k++) {
            const float* pc_row = cur + (k + 1) * WW;
            const float* pn_row = nxt + (k + 1) * WW;
            const float4 pC = *(const float4*)(pc_row + w0);
            const float4 pN = *(const float4*)(pn_row + w0);
            const float  pR = pc_row[idxR];

            const float pc[4] = { pC.x, pC.y, pC.z, pC.w };
            const float pn[4] = { pN.x, pN.y, pN.z, pN.w };
            const float pr[4] = { pC.y, pC.z, pC.w, pR  };

            float n = 0.0f, d = 0.0f;
#pragma unroll
            for (int j = 0; j < 4; j++) {
                // pxp + pyp = (pn + pr) - 2*pc
                const float s2  = pn[j] + pr[j];
                const float dif = fmaf(-2.0f, pc[j], s2);
                n += pc[j] * fmaf(wE[j], dif, pc[j]);
                d += pc[j] * tE[j];
            }
            nom[k] += n;
            den[k] += d;
        }

        __syncthreads();   // all reads of the stage we overwrite next iter are done
    }

    // ---- Block reduction of the 16 quantities ----
    __shared__ float sred[8][16];
    const int lane = threadIdx.x & 31;
    const int warp = threadIdx.x >> 5;

#pragma unroll
    for (int q = 0; q < 16; q++) {
        float v = (q < 8) ? nom[q] : den[q - 8];
#pragma unroll
        for (int off = 16; off > 0; off >>= 1)
            v += __shfl_xor_sync(0xFFFFFFFFu, v, off);
        if (lane == 0) sred[warp][q] = v;
    }
    __syncthreads();

    if (threadIdx.x < 16) {
        const int q = threadIdx.x;
        float v = 0.0f;
#pragma unroll
        for (int wp = 0; wp < 8; wp++) v += sred[wp][q];
        g_part[(size_t)blockIdx.y * (BB * 16) + b * 16 + q] = v;
    }

    // ---- Last-block finalize (ticket pattern; counter self-resets) ----
    __shared__ bool s_last;
    __threadfence();
    __syncthreads();
    if (threadIdx.x == 0) {
        unsigned int ticket = atomicAdd(&g_count, 1u);
        s_last = (ticket == NBLOCKS - 1);
    }
    __syncthreads();

    if (s_last) {
        __shared__ float s[256];
        __shared__ float c[BB * KK];
        const int t = threadIdx.x;
        const int q    = t & 127;
        const int half = t >> 7;

        float v = 0.0f;
#pragma unroll 8
        for (int y = half * (NBY / 2); y < (half + 1) * (NBY / 2); y++)
            v += g_part[(size_t)y * (BB * 16) + q];
        s[t] = v;
        __syncthreads();

        if (t < BB * KK) {
            const int bb = t >> 3, kk = t & 7;
            const float tn = s[bb * 16 + kk]     + s[128 + bb * 16 + kk];
            const float td = s[bb * 16 + 8 + kk] + s[128 + bb * 16 + 8 + kk];
            c[t] = tn / td;                // cut_cost[b,k]
        }
        __syncthreads();

        if (t == 0) {
            float sum = 0.0f;
            for (int j = 0; j < BB * KK; j++) sum += c[j];
            out[0] = (float)(BB * KK) - sum;
            g_count = 0;                   // reset for next graph replay
        }
    }
}

extern "C" void kernel_launch(void* const* d_in, const int* in_sizes, int n_in,
                              void* d_out, int out_size) {
    const float* img     = (const float*)d_in[0];  // (8,1,1024,1024)
    const float* spacing = (const float*)d_in[1];  // (2,)
    const float* p       = (const float*)d_in[2];  // (8,8,1024,1024)
    float* out = (float*)d_out;

    cudaFuncSetAttribute(clustering_fused_kernel,
                         cudaFuncAttributeMaxDynamicSharedMemorySize, DYN_SMEM);

    dim3 grid(1, NBY, BB);   // (1, 128, 8) = 1024 blocks
    clustering_fused_kernel<<<grid, 256, DYN_SMEM>>>(img, spacing, p, out);
}

// round 9
// speedup vs baseline: 1.0261x; 1.0261x over previous
#include <cuda_runtime.h>
#include <cuda_bf16.h>

// Fixed shapes from setup_inputs
#define BB 8
#define KK 8
#define KH 4                  // channels per block (K split across 2 blocks)
#define HH 1024
#define WW 1024
#define CH 8                  // rows per block chunk
#define NBY (HH / CH)         // 128 blocks along H
#define NBLOCKS (NBY * BB * 2)  // 2048 total
#define GAMMA_C 10.0f
#define EPS_SQRT_C 1e-24f

// Per-block partials: [y][b*16 + half*8 + q]; q<4: nom[kk=q], q>=4: den[kk=q-4]
__device__ float g_part[NBY * BB * 16];
__device__ unsigned int g_count = 0;   // zero-init; last block resets it

__global__ __launch_bounds__(256, 3) void clustering_fused_kernel(
    const float* __restrict__ img,      // (B,1,H,W)
    const float* __restrict__ spacing,  // (2,)
    const float* __restrict__ p,        // (B,K,H,W)
    float* __restrict__ out)
{
    const int b    = blockIdx.z;
    const int half = blockIdx.x;             // which K half
    const int h0   = blockIdx.y * CH;
    const int w0   = 4 * threadIdx.x;        // 256 threads cover W=1024 via float4
    const int lane = threadIdx.x & 31;
    const bool lastcol = (w0 + 4 >= WW);

    const float sx = spacing[0];
    const float sy = spacing[1];
    const float smin   = fminf(sx, sy);
    const float inv_sx = 1.0f / sx;
    const float inv_sy = 1.0f / sy;

    const float* __restrict__ Ib = img + (size_t)b * HH * WW;
    const float* __restrict__ pb = p + (size_t)b * KK * HH * WW
                                     + (size_t)half * KH * HH * WW;

    float nom[KH], den[KH];
#pragma unroll
    for (int k = 0; k < KH; k++) { nom[k] = 0.0f; den[k] = 0.0f; }

    // Prime current row registers (row h0)
    float4 iC = *(const float4*)(Ib + (size_t)h0 * WW + w0);
    float4 pC[KH];
#pragma unroll
    for (int k = 0; k < KH; k++)
        pC[k] = *(const float4*)(pb + (size_t)k * HH * WW + (size_t)h0 * WW + w0);

    for (int r = 0; r < CH; r++) {
        const int h  = h0 + r;
        const int hp = (h + 1 < HH) ? (h + 1) : (HH - 1);

        // ---- issue all 5 next-row loads up front (batched -> high MLP) ----
        float4 iN = *(const float4*)(Ib + (size_t)hp * WW + w0);
        float4 pN[KH];
#pragma unroll
        for (int k = 0; k < KH; k++)
            pN[k] = *(const float4*)(pb + (size_t)k * HH * WW + (size_t)hp * WW + w0);

        // ---- right-neighbor of current I row: shuffle of REGISTER state ----
        float iR = __shfl_down_sync(0xFFFFFFFFu, iC.x, 1);
        if (lane == 31)
            iR = lastcol ? iC.w : __ldg(Ib + (size_t)h * WW + w0 + 4);

        // ---- edge weights + (1+2w), reused across the channels ----
        float wE[4], tE[4];
        {
            const float ix[4] = { iN.x - iC.x, iN.y - iC.y, iN.z - iC.z, iN.w - iC.w };
            const float iy[4] = { iC.y - iC.x, iC.z - iC.y, iC.w - iC.z, iR   - iC.w };
#pragma unroll
            for (int j = 0; j < 4; j++) {
                const float gx  = ix[j] * inv_sx;
                const float gy  = iy[j] * inv_sy;
                const float gn2 = gx * gx + gy * gy;
                const float gnI = sqrtf(fmaxf(gn2, EPS_SQRT_C));
                wE[j] = 1.0f / (1.0f + GAMMA_C * gnI * smin);
                tE[j] = 1.0f + 2.0f * wE[j];
            }
        }

#pragma unroll
        for (int k = 0; k < KH; k++) {
            // shuffle reads register-resident row (no fresh-load dependency)
            float pR = __shfl_down_sync(0xFFFFFFFFu, pC[k].x, 1);
            if (lane == 31)
                pR = lastcol ? pC[k].w
                             : __ldg(pb + (size_t)k * HH * WW + (size_t)h * WW + w0 + 4);

            const float pc[4] = { pC[k].x, pC[k].y, pC[k].z, pC[k].w };
            const float pn[4] = { pN[k].x, pN[k].y, pN[k].z, pN[k].w };
            const float pr[4] = { pC[k].y, pC[k].z, pC[k].w, pR };

            float n = 0.0f, d = 0.0f;
#pragma unroll
            for (int j = 0; j < 4; j++) {
                // pxp + pyp = (pn + pr) - 2*pc
                const float s2  = pn[j] + pr[j];
                const float dif = fmaf(-2.0f, pc[j], s2);
                n += pc[j] * fmaf(wE[j], dif, pc[j]);
                d += pc[j] * tE[j];
            }
            nom[k] += n;
            den[k] += d;

            pC[k] = pN[k];   // roll row registers
        }
        iC = iN;
    }

    // ---- Block reduction of the 8 quantities ----
    __shared__ float sred[8][8];
    const int warp = threadIdx.x >> 5;

#pragma unroll
    for (int q = 0; q < 8; q++) {
        float v = (q < 4) ? nom[q] : den[q - 4];
#pragma unroll
        for (int off = 16; off > 0; off >>= 1)
            v += __shfl_xor_sync(0xFFFFFFFFu, v, off);
        if (lane == 0) sred[warp][q] = v;
    }
    __syncthreads();

    if (threadIdx.x < 8) {
        const int q = threadIdx.x;
        float v = 0.0f;
#pragma unroll
        for (int wp = 0; wp < 8; wp++) v += sred[wp][q];
        g_part[(size_t)blockIdx.y * (BB * 16) + b * 16 + half * 8 + q] = v;
    }

    // ---- Last-block finalize (ticket pattern; counter self-resets) ----
    __shared__ bool s_last;
    __threadfence();
    __syncthreads();
    if (threadIdx.x == 0) {
        unsigned int ticket = atomicAdd(&g_count, 1u);
        s_last = (ticket == NBLOCKS - 1);
    }
    __syncthreads();

    if (s_last) {
        __shared__ float s[256];
        __shared__ float c[BB * KK];
        const int t = threadIdx.x;
        const int q  = t & 127;
        const int hy = t >> 7;

        float v = 0.0f;
#pragma unroll 8
        for (int y = hy * (NBY / 2); y < (hy + 1) * (NBY / 2); y++)
            v += g_part[(size_t)y * (BB * 16) + q];
        s[t] = v;
        __syncthreads();

        if (t < BB * KK) {
            const int bb = t >> 3, k = t & 7;
            const int hf = k >> 2, kk = k & 3;
            const int cn = bb * 16 + hf * 8 + kk;       // nom combo
            const int cd = cn + 4;                      // den combo
            const float tn = s[cn] + s[128 + cn];
            const float td = s[cd] + s[128 + cd];
            c[t] = tn / td;                // cut_cost[b,k]
        }
        __syncthreads();

        if (t == 0) {
            float sum = 0.0f;
            for (int j = 0; j < BB * KK; j++) sum += c[j];
            out[0] = (float)(BB * KK) - sum;
            g_count = 0;                   // reset for next graph replay
        }
    }
}

extern "C" void kernel_launch(void* const* d_in, const int* in_sizes, int n_in,
                              void* d_out, int out_size) {
    const float* img     = (const float*)d_in[0];  // (8,1,1024,1024)
    const float* spacing = (const float*)d_in[1];  // (2,)
    const float* p       = (const float*)d_in[2];  // (8,8,1024,1024)
    float* out = (float*)d_out;

    dim3 grid(2, NBY, BB);   // (2, 128, 8) = 2048 blocks
    clustering_fused_kernel<<<grid, 256>>>(img, spacing, p, out);
}

// round 10
// speedup vs baseline: 1.0588x; 1.0319x over previous
#include <cuda_runtime.h>
#include <cuda_bf16.h>

// Fixed shapes from setup_inputs
#define BB 8
#define KK 8
#define KH 4                  // channels per block (K split across 2 blocks)
#define HH 1024
#define WW 1024
#define CH 8                  // rows per block chunk
#define NBY (HH / CH)         // 128 blocks along H
#define NBLOCKS (NBY * BB * 2)  // 2048 total
#define GAMMA_C 10.0f
#define EPS_SQRT_C 1e-24f

// Per-block partials: [y][b*16 + half*8 + q]; q<4: nom[kk=q], q>=4: den[kk=q-4]
__device__ float g_part[NBY * BB * 16];
__device__ unsigned int g_count = 0;   // zero-init; last block resets it

__global__ __launch_bounds__(256, 3) void clustering_fused_kernel(
    const float* __restrict__ img,      // (B,1,H,W)
    const float* __restrict__ spacing,  // (2,)
    const float* __restrict__ p,        // (B,K,H,W)
    float* __restrict__ out)
{
    const int b    = blockIdx.z;
    const int half = blockIdx.x;             // which K half
    const int h0   = blockIdx.y * CH;
    const int w0   = 4 * threadIdx.x;        // 256 threads cover W=1024 via float4
    // right-neighbor column, clamped: last thread reads its own .w element
    const int idxR = (w0 + 4 < WW) ? (w0 + 4) : (WW - 1);

    const float sx = spacing[0];
    const float sy = spacing[1];
    const float smin   = fminf(sx, sy);
    const float inv_sx = 1.0f / sx;
    const float inv_sy = 1.0f / sy;

    const float* __restrict__ Ib = img + (size_t)b * HH * WW;
    const float* __restrict__ pb = p + (size_t)b * KK * HH * WW
                                     + (size_t)half * KH * HH * WW;

    float nom[KH], den[KH];
#pragma unroll
    for (int k = 0; k < KH; k++) { nom[k] = 0.0f; den[k] = 0.0f; }

    // Prime current row registers (row h0)
    float4 iC = *(const float4*)(Ib + (size_t)h0 * WW + w0);
    float4 pC[KH];
#pragma unroll
    for (int k = 0; k < KH; k++)
        pC[k] = *(const float4*)(pb + (size_t)k * HH * WW + (size_t)h0 * WW + w0);

    for (int r = 0; r < CH; r++) {
        const int h  = h0 + r;
        const int hp = (h + 1 < HH) ? (h + 1) : (HH - 1);
        const size_t offC = (size_t)h  * WW;
        const size_t offN = (size_t)hp * WW;

        // ---- one batch of 10 independent loads ----
        //   5 x float4 next-row (DRAM stream) + 5 x scalar right-neighbor
        //   of current row (L1 hit: row h was streamed last iteration).
        float4 iN = *(const float4*)(Ib + offN + w0);
        float  iR = Ib[offC + idxR];
        float4 pN[KH];
        float  pR[KH];
#pragma unroll
        for (int k = 0; k < KH; k++) {
            const float* __restrict__ pk = pb + (size_t)k * HH * WW;
            pN[k] = *(const float4*)(pk + offN + w0);
            pR[k] = pk[offC + idxR];
        }

        // ---- edge weights + (1+2w), reused across the channels ----
        float wE[4], tE[4];
        {
            const float ix[4] = { iN.x - iC.x, iN.y - iC.y, iN.z - iC.z, iN.w - iC.w };
            const float iy[4] = { iC.y - iC.x, iC.z - iC.y, iC.w - iC.z, iR   - iC.w };
#pragma unroll
            for (int j = 0; j < 4; j++) {
                const float gx  = ix[j] * inv_sx;
                const float gy  = iy[j] * inv_sy;
                const float gn2 = gx * gx + gy * gy;
                const float gnI = sqrtf(fmaxf(gn2, EPS_SQRT_C));
                wE[j] = 1.0f / (1.0f + GAMMA_C * gnI * smin);
                tE[j] = 1.0f + 2.0f * wE[j];
            }
        }

#pragma unroll
        for (int k = 0; k < KH; k++) {
            const float pc[4] = { pC[k].x, pC[k].y, pC[k].z, pC[k].w };
            const float pn[4] = { pN[k].x, pN[k].y, pN[k].z, pN[k].w };
            const float pr[4] = { pC[k].y, pC[k].z, pC[k].w, pR[k] };

            float n = 0.0f, d = 0.0f;
#pragma unroll
            for (int j = 0; j < 4; j++) {
                // pxp + pyp = (pn + pr) - 2*pc
                const float s2  = pn[j] + pr[j];
                const float dif = fmaf(-2.0f, pc[j], s2);
                n += pc[j] * fmaf(wE[j], dif, pc[j]);
                d += pc[j] * tE[j];
            }
            nom[k] += n;
            den[k] += d;

            pC[k] = pN[k];   // roll row registers
        }
        iC = iN;
    }

    // ---- Block reduction of the 8 quantities ----
    __shared__ float sred[8][8];
    const int lane = threadIdx.x & 31;
    const int warp = threadIdx.x >> 5;

#pragma unroll
    for (int q = 0; q < 8; q++) {
        float v = (q < 4) ? nom[q] : den[q - 4];
#pragma unroll
        for (int off = 16; off > 0; off >>= 1)
            v += __shfl_xor_sync(0xFFFFFFFFu, v, off);
        if (lane == 0) sred[warp][q] = v;
    }
    __syncthreads();

    if (threadIdx.x < 8) {
        const int q = threadIdx.x;
        float v = 0.0f;
#pragma unroll
        for (int wp = 0; wp < 8; wp++) v += sred[wp][q];
        g_part[(size_t)blockIdx.y * (BB * 16) + b * 16 + half * 8 + q] = v;
    }

    // ---- Last-block finalize (ticket pattern; counter self-resets) ----
    __shared__ bool s_last;
    __threadfence();
    __syncthreads();
    if (threadIdx.x == 0) {
        unsigned int ticket = atomicAdd(&g_count, 1u);
        s_last = (ticket == NBLOCKS - 1);
    }
    __syncthreads();

    if (s_last) {
        __shared__ float s[256];
        __shared__ float c[BB * KK];
        const int t = threadIdx.x;
        const int q  = t & 127;
        const int hy = t >> 7;

        float v = 0.0f;
#pragma unroll 8
        for (int y = hy * (NBY / 2); y < (hy + 1) * (NBY / 2); y++)
            v += g_part[(size_t)y * (BB * 16) + q];
        s[t] = v;
        __syncthreads();

        if (t < BB * KK) {
            const int bb = t >> 3, k = t & 7;
            const int hf = k >> 2, kk = k & 3;
            const int cn = bb * 16 + hf * 8 + kk;       // nom combo
            const int cd = cn + 4;                      // den combo
            const float tn = s[cn] + s[128 + cn];
            const float td = s[cd] + s[128 + cd];
            c[t] = tn / td;                // cut_cost[b,k]
        }
        __syncthreads();

        if (t == 0) {
            float sum = 0.0f;
            for (int j = 0; j < BB * KK; j++) sum += c[j];
            out[0] = (float)(BB * KK) - sum;
            g_count = 0;                   // reset for next graph replay
        }
    }
}

extern "C" void kernel_launch(void* const* d_in, const int* in_sizes, int n_in,
                              void* d_out, int out_size) {
    const float* img     = (const float*)d_in[0];  // (8,1,1024,1024)
    const float* spacing = (const float*)d_in[1];  // (2,)
    const float* p       = (const float*)d_in[2];  // (8,8,1024,1024)
    float* out = (float*)d_out;

    dim3 grid(2, NBY, BB);   // (2, 128, 8) = 2048 blocks
    clustering_fused_kernel<<<grid, 256>>>(img, spacing, p, out);
}

// round 11
// speedup vs baseline: 1.0661x; 1.0069x over previous
#include <cuda_runtime.h>
#include <cuda_bf16.h>

// Fixed shapes from setup_inputs
#define BB 8
#define KK 8
#define KH 4                  // channels per block (K split across 2 blocks)
#define HH 1024
#define WW 1024
#define CH 8                  // rows per block chunk
#define NBY (HH / CH)         // 128 blocks along H
#define NBLOCKS (NBY * BB * 2)  // 2048 total
#define GAMMA_C 10.0f
#define EPS_SQRT_C 1e-24f

typedef unsigned long long u64;

// ---- Blackwell packed f32x2 helpers ----
__device__ __forceinline__ u64 pk2(float lo, float hi) {
    u64 r; asm("mov.b64 %0, {%1, %2};" : "=l"(r) : "f"(lo), "f"(hi)); return r;
}
__device__ __forceinline__ void upk2(u64 v, float& lo, float& hi) {
    asm("mov.b64 {%0, %1}, %2;" : "=f"(lo), "=f"(hi) : "l"(v));
}
__device__ __forceinline__ u64 add2(u64 a, u64 b) {
    u64 d; asm("add.rn.f32x2 %0, %1, %2;" : "=l"(d) : "l"(a), "l"(b)); return d;
}
__device__ __forceinline__ u64 mul2(u64 a, u64 b) {
    u64 d; asm("mul.rn.f32x2 %0, %1, %2;" : "=l"(d) : "l"(a), "l"(b)); return d;
}
__device__ __forceinline__ u64 fma2(u64 a, u64 b, u64 c) {
    u64 d; asm("fma.rn.f32x2 %0, %1, %2, %3;" : "=l"(d) : "l"(a), "l"(b), "l"(c)); return d;
}

// Per-block partials: [y][b*16 + half*8 + q]; q<4: nom[kk=q], q>=4: den[kk=q-4]
__device__ float g_part[NBY * BB * 16];
__device__ unsigned int g_count = 0;   // zero-init; last block resets it

__global__ __launch_bounds__(256, 3) void clustering_fused_kernel(
    const float* __restrict__ img,      // (B,1,H,W)
    const float* __restrict__ spacing,  // (2,)
    const float* __restrict__ p,        // (B,K,H,W)
    float* __restrict__ out)
{
    const int b    = blockIdx.z;
    const int half = blockIdx.x;             // which K half
    const int h0   = blockIdx.y * CH;
    const int w0   = 4 * threadIdx.x;        // 256 threads cover W=1024 via float4
    const int idxR = (w0 + 4 < WW) ? (w0 + 4) : (WW - 1);  // clamped right col

    const float sx = spacing[0];
    const float sy = spacing[1];
    const float smin   = fminf(sx, sy);
    const float gsmin  = GAMMA_C * smin;
    const float inv_sx = 1.0f / sx;
    const float inv_sy = 1.0f / sy;

    const u64 ISX2 = pk2(inv_sx, inv_sx);
    const u64 ISY2 = pk2(inv_sy, inv_sy);
    const u64 NEG1 = pk2(-1.0f, -1.0f);
    const u64 NEG2 = pk2(-2.0f, -2.0f);

    const float* __restrict__ Ib = img + (size_t)b * HH * WW;
    const float* __restrict__ pb = p + (size_t)b * KK * HH * WW
                                     + (size_t)half * KH * HH * WW;

    u64 nom2[KH], den2[KH];
    const u64 Z = pk2(0.0f, 0.0f);
#pragma unroll
    for (int k = 0; k < KH; k++) { nom2[k] = Z; den2[k] = Z; }

    // Prime current row registers (row h0)
    float4 iC = *(const float4*)(Ib + (size_t)h0 * WW + w0);
    float4 pC[KH];
#pragma unroll
    for (int k = 0; k < KH; k++)
        pC[k] = *(const float4*)(pb + (size_t)k * HH * WW + (size_t)h0 * WW + w0);

    for (int r = 0; r < CH; r++) {
        const int h  = h0 + r;
        const int hp = (h + 1 < HH) ? (h + 1) : (HH - 1);
        const size_t offC = (size_t)h  * WW;
        const size_t offN = (size_t)hp * WW;

        // ---- one batch of 10 independent loads ----
        float4 iN = *(const float4*)(Ib + offN + w0);
        float  iR = Ib[offC + idxR];
        float4 pN[KH];
        float  pR[KH];
#pragma unroll
        for (int k = 0; k < KH; k++) {
            const float* __restrict__ pk_ = pb + (size_t)k * HH * WW;
            pN[k] = *(const float4*)(pk_ + offN + w0);
            pR[k] = pk_[offC + idxR];
        }

        // ---- edge weights (packed gradient math, scalar MUFU tail) ----
        u64 wE01, wE23, tE01, tE23;
        {
            const u64 ic01 = pk2(iC.x, iC.y), ic23 = pk2(iC.z, iC.w);
            const u64 in01 = pk2(iN.x, iN.y), in23 = pk2(iN.z, iN.w);
            const u64 ir01 = pk2(iC.y, iC.z), ir23 = pk2(iC.w, iR);

            const u64 ix01 = fma2(ic01, NEG1, in01);   // iN - iC
            const u64 ix23 = fma2(ic23, NEG1, in23);
            const u64 iy01 = fma2(ic01, NEG1, ir01);   // right - center
            const u64 iy23 = fma2(ic23, NEG1, ir23);

            const u64 gx01 = mul2(ix01, ISX2), gx23 = mul2(ix23, ISX2);
            const u64 gy01 = mul2(iy01, ISY2), gy23 = mul2(iy23, ISY2);
            const u64 gn01 = fma2(gy01, gy01, mul2(gx01, gx01));
            const u64 gn23 = fma2(gy23, gy23, mul2(gx23, gx23));

            float g0, g1, g2, g3;
            upk2(gn01, g0, g1); upk2(gn23, g2, g3);
            const float w0_ = 1.0f / fmaf(gsmin, sqrtf(fmaxf(g0, EPS_SQRT_C)), 1.0f);
            const float w1_ = 1.0f / fmaf(gsmin, sqrtf(fmaxf(g1, EPS_SQRT_C)), 1.0f);
            const float w2_ = 1.0f / fmaf(gsmin, sqrtf(fmaxf(g2, EPS_SQRT_C)), 1.0f);
            const float w3_ = 1.0f / fmaf(gsmin, sqrtf(fmaxf(g3, EPS_SQRT_C)), 1.0f);
            wE01 = pk2(w0_, w1_); wE23 = pk2(w2_, w3_);
            tE01 = pk2(fmaf(2.0f, w0_, 1.0f), fmaf(2.0f, w1_, 1.0f));
            tE23 = pk2(fmaf(2.0f, w2_, 1.0f), fmaf(2.0f, w3_, 1.0f));
        }

#pragma unroll
        for (int k = 0; k < KH; k++) {
            const u64 pc01 = pk2(pC[k].x, pC[k].y), pc23 = pk2(pC[k].z, pC[k].w);
            const u64 pr01 = pk2(pC[k].y, pC[k].z), pr23 = pk2(pC[k].w, pR[k]);
            const u64 pn01 = pk2(pN[k].x, pN[k].y), pn23 = pk2(pN[k].z, pN[k].w);

            // dif = (pn + pr) - 2*pc ;  nom += pc*(pc + wE*dif) ;  den += pc*(1+2wE)
            const u64 s01 = add2(pn01, pr01), s23 = add2(pn23, pr23);
            const u64 d01 = fma2(NEG2, pc01, s01), d23 = fma2(NEG2, pc23, s23);
            const u64 t01 = fma2(wE01, d01, pc01), t23 = fma2(wE23, d23, pc23);
            nom2[k] = fma2(pc01, t01, nom2[k]);
            nom2[k] = fma2(pc23, t23, nom2[k]);
            den2[k] = fma2(pc01, tE01, den2[k]);
            den2[k] = fma2(pc23, tE23, den2[k]);

            pC[k] = pN[k];   // roll row registers
        }
        iC = iN;
    }

    // ---- horizontal add of packed accumulators ----
    float nom[KH], den[KH];
#pragma unroll
    for (int k = 0; k < KH; k++) {
        float a, b2;
        upk2(nom2[k], a, b2); nom[k] = a + b2;
        upk2(den2[k], a, b2); den[k] = a + b2;
    }

    // ---- Block reduction of the 8 quantities ----
    __shared__ float sred[8][8];
    const int lane = threadIdx.x & 31;
    const int warp = threadIdx.x >> 5;

#pragma unroll
    for (int q = 0; q < 8; q++) {
        float v = (q < 4) ? nom[q] : den[q - 4];
#pragma unroll
        for (int off = 16; off > 0; off >>= 1)
            v += __shfl_xor_sync(0xFFFFFFFFu, v, off);
        if (lane == 0) sred[warp][q] = v;
    }
    __syncthreads();

    if (threadIdx.x < 8) {
        const int q = threadIdx.x;
        float v = 0.0f;
#pragma unroll
        for (int wp = 0; wp < 8; wp++) v += sred[wp][q];
        g_part[(size_t)blockIdx.y * (BB * 16) + b * 16 + half * 8 + q] = v;
    }

    // ---- Last-block finalize (ticket pattern; counter self-resets) ----
    __shared__ bool s_last;
    __threadfence();
    __syncthreads();
    if (threadIdx.x == 0) {
        unsigned int ticket = atomicAdd(&g_count, 1u);
        s_last = (ticket == NBLOCKS - 1);
    }
    __syncthreads();

    if (s_last) {
        __shared__ float s[256];
        __shared__ float c[BB * KK];
        const int t = threadIdx.x;
        const int q  = t & 127;
        const int hy = t >> 7;

        float v = 0.0f;
#pragma unroll 8
        for (int y = hy * (NBY / 2); y < (hy + 1) * (NBY / 2); y++)
            v += g_part[(size_t)y * (BB * 16) + q];
        s[t] = v;
        __syncthreads();

        if (t < BB * KK) {
            const int bb = t >> 3, k = t & 7;
            const int hf = k >> 2, kk = k & 3;
            const int cn = bb * 16 + hf * 8 + kk;       // nom combo
            const int cd = cn + 4;                      // den combo
            const float tn = s[cn] + s[128 + cn];
            const float td = s[cd] + s[128 + cd];
            c[t] = tn / td;                // cut_cost[b,k]
        }
        __syncthreads();

        if (t == 0) {
            float sum = 0.0f;
            for (int j = 0; j < BB * KK; j++) sum += c[j];
            out[0] = (float)(BB * KK) - sum;
            g_count = 0;                   // reset for next graph replay
        }
    }
}

extern "C" void kernel_launch(void* const* d_in, const int* in_sizes, int n_in,
                              void* d_out, int out_size) {
    const float* img     = (const float*)d_in[0];  // (8,1,1024,1024)
    const float* spacing = (const float*)d_in[1];  // (2,)
    const float* p       = (const float*)d_in[2];  // (8,8,1024,1024)
    float* out = (float*)d_out;

    dim3 grid(2, NBY, BB);   // (2, 128, 8) = 2048 blocks
    clustering_fused_kernel<<<grid, 256>>>(img, spacing, p, out);
}